// round 5
// baseline (speedup 1.0000x reference)
#include <cuda_runtime.h>
#include <stdint.h>

// Problem dims (fixed by the reference)
#define B_DIM   8
#define S_LEN   2048
#define D_DIM   1024
#define P_DIM   256
#define NQ_DIM  8192

#define M_TOT   (B_DIM * S_LEN)   // 16384
#define N_TOT   P_DIM             // 256
#define K_TOT   D_DIM             // 1024

// GEMM tile config
#define BM 128
#define BN 64
#define BK 16
#define AS_LD (BM + 4)            // pad to soften STS bank conflicts
#define NTHREADS 256

// Scratch for h = enc @ W + b  (16 MB, static device array: no allocs allowed)
__device__ float g_h[(size_t)M_TOT * N_TOT];

__device__ __forceinline__ float2 unpack_f32x2(unsigned long long v) {
    float2 r;
    r.x = __uint_as_float((unsigned int)(v & 0xffffffffull));
    r.y = __uint_as_float((unsigned int)(v >> 32));
    return r;
}

// acc (f32x2) += a2 (f32x2) * b2 (f32x2), lanewise packed FMA (sm_100+)
#define FMA2(acc, a2, b2) \
    asm volatile("fma.rn.f32x2 %0, %1, %2, %0;" : "+l"(acc) : "l"(a2), "l"(b2))

#define PACK2(dst, lo, hi) \
    asm volatile("mov.b64 %0, {%1, %2};" : "=l"(dst) : "f"(lo), "f"(hi))

// ---------------------------------------------------------------------------
// GEMM: h[M, 256] = A[M, 1024] @ W[1024, 256] + bias, fp32 via f32x2 FMA.
// Grid (N_TOT/BN, M_TOT/BM) = (4, 128), 256 threads.
// Thread (ty,tx): rows ty*8..+7 (as 4 f32x2 row-pairs), cols tx*4..+3.
// ---------------------------------------------------------------------------
__global__ void __launch_bounds__(NTHREADS)
gemm_bias_kernel(const float* __restrict__ A,
                 const float* __restrict__ W,
                 const float* __restrict__ bias) {
    __shared__ float As[2][BK][AS_LD];
    __shared__ float Bs[2][BK][BN];

    const int tid = threadIdx.x;
    const int m_base = blockIdx.y * BM;
    const int n_base = blockIdx.x * BN;

    // A tile load mapping: 128x16 floats = 512 float4; 2 float4 per thread
    const int a_row = tid >> 2;            // 0..63 (and +64)
    const int a_col = (tid & 3) * 4;       // 0,4,8,12
    // W tile load mapping: 16x64 floats = 256 float4; 1 per thread
    const int b_row = tid >> 4;            // 0..15
    const int b_col = (tid & 15) * 4;      // 0..60

    const float* Aptr = A + (size_t)(m_base + a_row) * K_TOT + a_col;
    const float* Wptr = W + (size_t)b_row * N_TOT + n_base + b_col;

    const int ty = tid >> 4;               // 0..15 -> rows ty*8..+7
    const int tx = tid & 15;               // 0..15 -> cols tx*4..+3
    const int r0 = ty * 8;
    const int c0 = tx * 4;

    unsigned long long acc[4][4];
    #pragma unroll
    for (int i = 0; i < 4; i++)
        #pragma unroll
        for (int j = 0; j < 4; j++) acc[i][j] = 0ull;

    // ---- prologue: load tile 0 into regs, stage to smem buf 0 ----
    float4 ra0 = *(const float4*)(Aptr);
    float4 ra1 = *(const float4*)(Aptr + (size_t)64 * K_TOT);
    float4 rb  = *(const float4*)(Wptr);

    {
        As[0][a_col + 0][a_row] = ra0.x;
        As[0][a_col + 1][a_row] = ra0.y;
        As[0][a_col + 2][a_row] = ra0.z;
        As[0][a_col + 3][a_row] = ra0.w;
        As[0][a_col + 0][a_row + 64] = ra1.x;
        As[0][a_col + 1][a_row + 64] = ra1.y;
        As[0][a_col + 2][a_row + 64] = ra1.z;
        As[0][a_col + 3][a_row + 64] = ra1.w;
        *(float4*)&Bs[0][b_row][b_col] = rb;
    }
    __syncthreads();

    const int KT = K_TOT / BK;  // 64
    for (int kt = 0; kt < KT; kt++) {
        const int buf = kt & 1;

        // prefetch next tile into regs (hides LDG under compute)
        if (kt + 1 < KT) {
            Aptr += BK;
            Wptr += (size_t)BK * N_TOT;
            ra0 = *(const float4*)(Aptr);
            ra1 = *(const float4*)(Aptr + (size_t)64 * K_TOT);
            rb  = *(const float4*)(Wptr);
        }

        // compute on current buffer
        #pragma unroll
        for (int k = 0; k < BK; k++) {
            float4 af0 = *(const float4*)&As[buf][k][r0];
            float4 af1 = *(const float4*)&As[buf][k][r0 + 4];
            float4 bf  = *(const float4*)&Bs[buf][k][c0];

            unsigned long long a2[4], b2[4];
            PACK2(a2[0], af0.x, af0.y);
            PACK2(a2[1], af0.z, af0.w);
            PACK2(a2[2], af1.x, af1.y);
            PACK2(a2[3], af1.z, af1.w);
            PACK2(b2[0], bf.x, bf.x);
            PACK2(b2[1], bf.y, bf.y);
            PACK2(b2[2], bf.z, bf.z);
            PACK2(b2[3], bf.w, bf.w);

            #pragma unroll
            for (int pi = 0; pi < 4; pi++) {
                FMA2(acc[pi][0], a2[pi], b2[0]);
                FMA2(acc[pi][1], a2[pi], b2[1]);
                FMA2(acc[pi][2], a2[pi], b2[2]);
                FMA2(acc[pi][3], a2[pi], b2[3]);
            }
        }

        // stage next tile into the other buffer
        if (kt + 1 < KT) {
            const int nb = buf ^ 1;
            As[nb][a_col + 0][a_row] = ra0.x;
            As[nb][a_col + 1][a_row] = ra0.y;
            As[nb][a_col + 2][a_row] = ra0.z;
            As[nb][a_col + 3][a_row] = ra0.w;
            As[nb][a_col + 0][a_row + 64] = ra1.x;
            As[nb][a_col + 1][a_row + 64] = ra1.y;
            As[nb][a_col + 2][a_row + 64] = ra1.z;
            As[nb][a_col + 3][a_row + 64] = ra1.w;
            *(float4*)&Bs[nb][b_row][b_col] = rb;
        }
        __syncthreads();
    }

    // ---- epilogue: bias + store to g_h ----
    float bs0 = bias[n_base + c0 + 0];
    float bs1 = bias[n_base + c0 + 1];
    float bs2 = bias[n_base + c0 + 2];
    float bs3 = bias[n_base + c0 + 3];

    #pragma unroll
    for (int pi = 0; pi < 4; pi++) {
        float2 v0 = unpack_f32x2(acc[pi][0]);
        float2 v1 = unpack_f32x2(acc[pi][1]);
        float2 v2 = unpack_f32x2(acc[pi][2]);
        float2 v3 = unpack_f32x2(acc[pi][3]);
        float4 lo, hi;
        lo.x = v0.x + bs0; lo.y = v1.x + bs1; lo.z = v2.x + bs2; lo.w = v3.x + bs3;
        hi.x = v0.y + bs0; hi.y = v1.y + bs1; hi.z = v2.y + bs2; hi.w = v3.y + bs3;
        const int m0 = m_base + r0 + 2 * pi;
        *(float4*)&g_h[(size_t)m0 * N_TOT + n_base + c0] = lo;
        *(float4*)&g_h[(size_t)(m0 + 1) * N_TOT + n_base + c0] = hi;
    }
}

// ---------------------------------------------------------------------------
// Gather: out[set][q][0:256] = h[qb, s], out[set][q][256:512] = h[qb, e],
// zeroed when e < s. Grid (NQ, 2), 128 threads; 1 float4 per thread.
// ---------------------------------------------------------------------------
__global__ void __launch_bounds__(128)
gather_kernel(const int* __restrict__ qb,
              const int* __restrict__ s1, const int* __restrict__ e1,
              const int* __restrict__ s2, const int* __restrict__ e2,
              float* __restrict__ out) {
    const int q   = blockIdx.x;
    const int set = blockIdx.y;
    const int* sp = set ? s2 : s1;
    const int* ep = set ? e2 : e1;
    const int s = sp[q];
    const int e = ep[q];
    const int b = qb[q];
    const int tid = threadIdx.x;  // 0..127, covers 512 floats

    float4 val = make_float4(0.f, 0.f, 0.f, 0.f);
    if (e >= s) {
        const int pos = (tid < 64) ? s : e;
        const int row = b * S_LEN + pos;
        const int col = (tid & 63) * 4;
        val = *(const float4*)&g_h[(size_t)row * N_TOT + col];
    }
    float* o = out + ((size_t)set * NQ_DIM + q) * (2 * P_DIM) + tid * 4;
    *(float4*)o = val;
}

// ---------------------------------------------------------------------------
// Inputs (metadata order): flag, encoded_input, start_ids_1, end_ids_1,
// query_batch_idx, start_ids_2, end_ids_2, W, b. Output: res1 then res2,
// each [NQ, 512] fp32, concatenated.
// ---------------------------------------------------------------------------
extern "C" void kernel_launch(void* const* d_in, const int* in_sizes, int n_in,
                              void* d_out, int out_size) {
    const float* enc  = (const float*)d_in[1];
    const int*   s1   = (const int*)d_in[2];
    const int*   e1   = (const int*)d_in[3];
    const int*   qb   = (const int*)d_in[4];
    const int*   s2   = (const int*)d_in[5];
    const int*   e2   = (const int*)d_in[6];
    const float* W    = (const float*)d_in[7];
    const float* bias = (const float*)d_in[8];
    float* out = (float*)d_out;

    dim3 ggrid(N_TOT / BN, M_TOT / BM);  // (4, 128)
    gemm_bias_kernel<<<ggrid, NTHREADS>>>(enc, W, bias);

    gather_kernel<<<dim3(NQ_DIM, 2), 128>>>(qb, s1, e1, s2, e2, out);
}

// round 9
// speedup vs baseline: 1.5332x; 1.5332x over previous
#include <cuda_runtime.h>
#include <cuda_bf16.h>
#include <stdint.h>

// Problem dims (fixed)
#define B_DIM   8
#define S_LEN   2048
#define D_DIM   1024
#define P_DIM   256
#define NQ_DIM  8192
#define M_TOT   16384
#define N_TOT   256
#define K_TOT   1024

// GEMM tiling
#define BM      128
#define BN      128
#define BK      32
#define KTILES  (K_TOT / BK)        // 32
#define LDA     40                  // bf16 elems per smem row (32 data + 8 pad) -> 80B stride
#define TILE_B  (128 * LDA * 2)     // 10240 bytes per tile
#define STAGE_B (4 * TILE_B)        // 40960 (Ah, Al, Wh, Wl)
#define SMEM_GEMM (2 * STAGE_B + 1024)  // 82944 incl bias

// Device scratch (static: no allocations allowed)
__device__ __align__(16) __nv_bfloat16 g_Ah[(size_t)M_TOT * K_TOT];   // 32 MB
__device__ __align__(16) __nv_bfloat16 g_Al[(size_t)M_TOT * K_TOT];   // 32 MB
__device__ __align__(16) __nv_bfloat16 g_Wth[(size_t)N_TOT * K_TOT];  // 512 KB (W^T hi)
__device__ __align__(16) __nv_bfloat16 g_Wtl[(size_t)N_TOT * K_TOT];  // 512 KB (W^T lo)
__device__ __align__(16) float         g_h[(size_t)M_TOT * N_TOT];    // 16 MB

// ---------------- helpers (baseline PTX only: sm_80-level) ----------------
__device__ __forceinline__ uint32_t smem_u32(const void* p) {
    uint32_t a;
    asm("{ .reg .u64 t; cvta.to.shared.u64 t, %1; cvt.u32.u64 %0, t; }" : "=r"(a) : "l"(p));
    return a;
}
__device__ __forceinline__ void cp_async16(uint32_t dst, const void* src) {
    asm volatile("cp.async.cg.shared.global [%0], [%1], 16;" :: "r"(dst), "l"(src) : "memory");
}
__device__ __forceinline__ void ldsm_x4(uint32_t* r, uint32_t addr) {
    asm volatile("ldmatrix.sync.aligned.m8n8.x4.shared.b16 {%0,%1,%2,%3}, [%4];"
                 : "=r"(r[0]), "=r"(r[1]), "=r"(r[2]), "=r"(r[3]) : "r"(addr));
}
__device__ __forceinline__ void mma16816(float* c, const uint32_t* a, uint32_t b0, uint32_t b1) {
    asm volatile(
        "mma.sync.aligned.m16n8k16.row.col.f32.bf16.bf16.f32 "
        "{%0,%1,%2,%3}, {%4,%5,%6,%7}, {%8,%9}, {%0,%1,%2,%3};"
        : "+f"(c[0]), "+f"(c[1]), "+f"(c[2]), "+f"(c[3])
        : "r"(a[0]), "r"(a[1]), "r"(a[2]), "r"(a[3]), "r"(b0), "r"(b1));
}
// hi = bf16_rn(x); lo = bf16_rn(x - hi)
__device__ __forceinline__ void split2(float x, float y, unsigned int& hw, unsigned int& lw) {
    __nv_bfloat16 hx = __float2bfloat16_rn(x);
    __nv_bfloat16 hy = __float2bfloat16_rn(y);
    __nv_bfloat162 hp; hp.x = hx; hp.y = hy;
    hw = *reinterpret_cast<unsigned int*>(&hp);
    __nv_bfloat162 lp = __floats2bfloat162_rn(x - __bfloat162float(hx),
                                              y - __bfloat162float(hy));
    lw = *reinterpret_cast<unsigned int*>(&lp);
}

// ---------------------------------------------------------------------------
// split_a: A[16384,1024] fp32 -> g_Ah/g_Al bf16 row-major. 8 elems/thread.
// ---------------------------------------------------------------------------
__global__ void __launch_bounds__(256)
split_a_kernel(const float* __restrict__ A) {
    int g = blockIdx.x * 256 + threadIdx.x;   // 0 .. 2M-1
    int m  = g >> 7;
    int k8 = g & 127;
    const float4* s4 = (const float4*)(A + (size_t)m * K_TOT + k8 * 8);
    float4 v0 = s4[0], v1 = s4[1];
    float a[8] = {v0.x, v0.y, v0.z, v0.w, v1.x, v1.y, v1.z, v1.w};
    unsigned int hw[4], lw[4];
    #pragma unroll
    for (int p = 0; p < 4; p++) split2(a[2*p], a[2*p+1], hw[p], lw[p]);
    size_t off = (size_t)m * K_TOT + k8 * 8;
    *(uint4*)(g_Ah + off) = make_uint4(hw[0], hw[1], hw[2], hw[3]);
    *(uint4*)(g_Al + off) = make_uint4(lw[0], lw[1], lw[2], lw[3]);
}

// ---------------------------------------------------------------------------
// split_w: W[1024,256] fp32 -> W^T hi/lo bf16 [256][1024] (k-contiguous).
// ---------------------------------------------------------------------------
__global__ void __launch_bounds__(256)
split_w_kernel(const float* __restrict__ W) {
    int t = blockIdx.x * 256 + threadIdx.x;   // 0 .. 32767
    int n  = t >> 7;
    int k8 = t & 127;
    unsigned int hw[4], lw[4];
    #pragma unroll
    for (int p = 0; p < 4; p++) {
        float x = W[(size_t)(k8 * 8 + 2 * p)     * N_TOT + n];
        float y = W[(size_t)(k8 * 8 + 2 * p + 1) * N_TOT + n];
        split2(x, y, hw[p], lw[p]);
    }
    size_t off = (size_t)n * K_TOT + k8 * 8;
    *(uint4*)(g_Wth + off) = make_uint4(hw[0], hw[1], hw[2], hw[3]);
    *(uint4*)(g_Wtl + off) = make_uint4(lw[0], lw[1], lw[2], lw[3]);
}

// ---------------------------------------------------------------------------
// GEMM: h = Ah@Wh^T + Ah@Wl^T + Al@Wh^T + bias via mma.sync bf16.
// Grid (2, 128), 256 threads (8 warps: 4m x 2n), 2-stage cp.async pipeline.
// ---------------------------------------------------------------------------
__device__ __forceinline__ void issue_stage(uint32_t st, int kt, int tid,
                                            const __nv_bfloat16* a_h,
                                            const __nv_bfloat16* a_l,
                                            const __nv_bfloat16* w_h,
                                            const __nv_bfloat16* w_l) {
    const int k0 = kt * BK;
    const __nv_bfloat16* gb[4] = {a_h, a_l, w_h, w_l};
    #pragma unroll
    for (int it = 0; it < 8; it++) {
        const int tile = it >> 1;
        const int w = ((it & 1) << 8) + tid;    // 0..511 within tile
        const int row = w >> 2, g = w & 3;
        uint32_t dst = st + tile * TILE_B + (uint32_t)(row * LDA + g * 8) * 2;
        const __nv_bfloat16* src = gb[tile] + (size_t)row * K_TOT + k0 + g * 8;
        cp_async16(dst, src);
    }
    asm volatile("cp.async.commit_group;" ::: "memory");
}

__global__ void __launch_bounds__(256, 2)
gemm_mma_kernel(const float* __restrict__ bias) {
    extern __shared__ char smem[];
    const uint32_t sb = smem_u32(smem);
    const int tid  = threadIdx.x;
    const int lane = tid & 31;
    const int wid  = tid >> 5;
    const int m0 = blockIdx.y * BM;
    const int n0 = blockIdx.x * BN;
    const int mw = (wid >> 1) * 32;   // warp m offset within CTA
    const int nw = (wid & 1) * 64;    // warp n offset within CTA

    float* bias_s = (float*)(smem + 2 * STAGE_B);
    if (tid < BN) bias_s[tid] = bias[n0 + tid];

    float acc[2][8][4];
    #pragma unroll
    for (int i = 0; i < 2; i++)
        #pragma unroll
        for (int j = 0; j < 8; j++)
            #pragma unroll
            for (int v = 0; v < 4; v++) acc[i][j][v] = 0.f;

    const __nv_bfloat16* a_h = g_Ah  + (size_t)m0 * K_TOT;
    const __nv_bfloat16* a_l = g_Al  + (size_t)m0 * K_TOT;
    const __nv_bfloat16* w_h = g_Wth + (size_t)n0 * K_TOT;
    const __nv_bfloat16* w_l = g_Wtl + (size_t)n0 * K_TOT;

    issue_stage(sb, 0, tid, a_h, a_l, w_h, w_l);

    const uint32_t a_row = lane & 15;
    const uint32_t a_g   = lane >> 4;

    for (int kt = 0; kt < KTILES; kt++) {
        const int s = kt & 1;
        if (kt + 1 < KTILES) {
            issue_stage(sb + (s ^ 1) * STAGE_B, kt + 1, tid, a_h, a_l, w_h, w_l);
            asm volatile("cp.async.wait_group 1;" ::: "memory");
        } else {
            asm volatile("cp.async.wait_group 0;" ::: "memory");
        }
        __syncthreads();

        const uint32_t st   = sb + s * STAGE_B;
        const uint32_t ah_b = st;
        const uint32_t al_b = st + TILE_B;
        const uint32_t wh_b = st + 2 * TILE_B;
        const uint32_t wl_b = st + 3 * TILE_B;

        #pragma unroll
        for (int k16 = 0; k16 < 2; k16++) {
            const uint32_t aoff = (uint32_t)((mw + a_row) * LDA + k16 * 16 + a_g * 8) * 2;
            uint32_t ah0[4], ah1[4], al0[4], al1[4];
            ldsm_x4(ah0, ah_b + aoff);
            ldsm_x4(ah1, ah_b + aoff + 16 * LDA * 2);
            ldsm_x4(al0, al_b + aoff);
            ldsm_x4(al1, al_b + aoff + 16 * LDA * 2);

            #pragma unroll
            for (int nq = 0; nq < 4; nq++) {
                const uint32_t woff =
                    (uint32_t)((nw + nq * 16 + a_row) * LDA + k16 * 16 + a_g * 8) * 2;
                uint32_t w4[4];
                ldsm_x4(w4, wh_b + woff);                 // Wh frags for n16
                mma16816(acc[0][2*nq],   ah0, w4[0], w4[2]);
                mma16816(acc[0][2*nq+1], ah0, w4[1], w4[3]);
                mma16816(acc[1][2*nq],   ah1, w4[0], w4[2]);
                mma16816(acc[1][2*nq+1], ah1, w4[1], w4[3]);
                mma16816(acc[0][2*nq],   al0, w4[0], w4[2]);   // Al @ Wh
                mma16816(acc[0][2*nq+1], al0, w4[1], w4[3]);
                mma16816(acc[1][2*nq],   al1, w4[0], w4[2]);
                mma16816(acc[1][2*nq+1], al1, w4[1], w4[3]);
                ldsm_x4(w4, wl_b + woff);                 // Wl frags
                mma16816(acc[0][2*nq],   ah0, w4[0], w4[2]);   // Ah @ Wl
                mma16816(acc[0][2*nq+1], ah0, w4[1], w4[3]);
                mma16816(acc[1][2*nq],   ah1, w4[0], w4[2]);
                mma16816(acc[1][2*nq+1], ah1, w4[1], w4[3]);
            }
        }
        __syncthreads();
    }

    // Epilogue: bias + store fp32 h
    const int crow = lane >> 2;        // 0..7
    const int ccol = (lane & 3) * 2;   // 0,2,4,6
    #pragma unroll
    for (int mt = 0; mt < 2; mt++) {
        const int mrow = m0 + mw + mt * 16 + crow;
        #pragma unroll
        for (int nt = 0; nt < 8; nt++) {
            const int nc = nw + nt * 8 + ccol;
            const float b0 = bias_s[nc], b1 = bias_s[nc + 1];
            float2 v0 = make_float2(acc[mt][nt][0] + b0, acc[mt][nt][1] + b1);
            float2 v1 = make_float2(acc[mt][nt][2] + b0, acc[mt][nt][3] + b1);
            *(float2*)&g_h[(size_t)mrow * N_TOT + n0 + nc] = v0;
            *(float2*)&g_h[(size_t)(mrow + 8) * N_TOT + n0 + nc] = v1;
        }
    }
}

// ---------------------------------------------------------------------------
// Gather: one q per 128-thread half-block, both sets per thread (MLP=2).
// ---------------------------------------------------------------------------
__global__ void __launch_bounds__(256)
gather_kernel(const int* __restrict__ qb,
              const int* __restrict__ s1, const int* __restrict__ e1,
              const int* __restrict__ s2, const int* __restrict__ e2,
              float* __restrict__ out) {
    const int q = blockIdx.x * 2 + (threadIdx.x >> 7);
    const int t = threadIdx.x & 127;
    const int b = __ldg(&qb[q]);
    const int sA = __ldg(&s1[q]), eA = __ldg(&e1[q]);
    const int sB = __ldg(&s2[q]), eB = __ldg(&e2[q]);
    const int col = (t & 63) * 4;
    const size_t brow = (size_t)b * S_LEN;

    float4 v0 = make_float4(0.f, 0.f, 0.f, 0.f);
    float4 v1 = v0;
    if (eA >= sA) {
        const int pos = (t < 64) ? sA : eA;
        v0 = *(const float4*)&g_h[(brow + pos) * N_TOT + col];
    }
    if (eB >= sB) {
        const int pos = (t < 64) ? sB : eB;
        v1 = *(const float4*)&g_h[(brow + pos) * N_TOT + col];
    }
    *(float4*)(out + ((size_t)q)          * (2 * P_DIM) + t * 4) = v0;
    *(float4*)(out + ((size_t)NQ_DIM + q) * (2 * P_DIM) + t * 4) = v1;
}

// ---------------------------------------------------------------------------
// Inputs: flag, encoded_input, start_ids_1, end_ids_1, query_batch_idx,
// start_ids_2, end_ids_2, W, b. Output: res1 then res2, each [NQ, 512] fp32.
// ---------------------------------------------------------------------------
extern "C" void kernel_launch(void* const* d_in, const int* in_sizes, int n_in,
                              void* d_out, int out_size) {
    const float* enc  = (const float*)d_in[1];
    const int*   s1   = (const int*)d_in[2];
    const int*   e1   = (const int*)d_in[3];
    const int*   qb   = (const int*)d_in[4];
    const int*   s2   = (const int*)d_in[5];
    const int*   e2   = (const int*)d_in[6];
    const float* W    = (const float*)d_in[7];
    const float* bias = (const float*)d_in[8];
    float* out = (float*)d_out;

    cudaFuncSetAttribute(gemm_mma_kernel,
                         cudaFuncAttributeMaxDynamicSharedMemorySize, SMEM_GEMM);

    split_a_kernel<<<(M_TOT * (K_TOT / 8)) / 256, 256>>>(enc);   // 8192 blocks
    split_w_kernel<<<(N_TOT * (K_TOT / 8)) / 256, 256>>>(W);     // 128 blocks
    gemm_mma_kernel<<<dim3(2, M_TOT / BM), 256, SMEM_GEMM>>>(bias);
    gather_kernel<<<NQ_DIM / 2, 256>>>(qb, s1, e1, s2, e2, out);
}

// round 11
// speedup vs baseline: 1.8809x; 1.2268x over previous
#include <cuda_runtime.h>
#include <cuda_bf16.h>
#include <stdint.h>

// Problem dims (fixed)
#define B_DIM   8
#define S_LEN   2048
#define D_DIM   1024
#define P_DIM   256
#define NQ_DIM  8192
#define M_TOT   16384
#define N_TOT   256
#define K_TOT   1024

// GEMM tiling: BM=128, BN=256 (full N), BK=32
#define BM      128
#define BN      256
#define BK      32
#define KTILES  (K_TOT / BK)        // 32
#define LDA     40                  // bf16 elems per smem row (32 data + 8 pad) -> 80B stride

#define A_TILE_B  (BM * LDA * 2)    // 10240  (one of Ah / Al)
#define W_TILE_B  (BN * LDA * 2)    // 20480  (one of Wh / Wl)
#define ASTG_B    (2 * A_TILE_B)    // 20480  per stage (Ah + Al)
#define WSTG_B    (2 * W_TILE_B)    // 40960  per stage (Wh + Wl)
#define SM_W0     (2 * ASTG_B)      // 40960
#define SM_BIAS   (SM_W0 + 2 * WSTG_B)   // 122880
#define SMEM_GEMM (SM_BIAS + 1024)       // 123904

// Device scratch (static: no allocations allowed)
__device__ __align__(16) __nv_bfloat16 g_Wth[(size_t)N_TOT * K_TOT];  // 512 KB (W^T hi)
__device__ __align__(16) __nv_bfloat16 g_Wtl[(size_t)N_TOT * K_TOT];  // 512 KB (W^T lo)
__device__ __align__(16) float         g_h[(size_t)M_TOT * N_TOT];    // 16 MB

// ---------------- helpers (baseline PTX only: sm_80-level) ----------------
__device__ __forceinline__ uint32_t smem_u32(const void* p) {
    uint32_t a;
    asm("{ .reg .u64 t; cvta.to.shared.u64 t, %1; cvt.u32.u64 %0, t; }" : "=r"(a) : "l"(p));
    return a;
}
__device__ __forceinline__ void cp_async16(uint32_t dst, const void* src) {
    asm volatile("cp.async.cg.shared.global [%0], [%1], 16;" :: "r"(dst), "l"(src) : "memory");
}
__device__ __forceinline__ void ldsm_x4(uint32_t* r, uint32_t addr) {
    asm volatile("ldmatrix.sync.aligned.m8n8.x4.shared.b16 {%0,%1,%2,%3}, [%4];"
                 : "=r"(r[0]), "=r"(r[1]), "=r"(r[2]), "=r"(r[3]) : "r"(addr));
}
__device__ __forceinline__ void mma16816(float* c, const uint32_t* a, uint32_t b0, uint32_t b1) {
    asm volatile(
        "mma.sync.aligned.m16n8k16.row.col.f32.bf16.bf16.f32 "
        "{%0,%1,%2,%3}, {%4,%5,%6,%7}, {%8,%9}, {%0,%1,%2,%3};"
        : "+f"(c[0]), "+f"(c[1]), "+f"(c[2]), "+f"(c[3])
        : "r"(a[0]), "r"(a[1]), "r"(a[2]), "r"(a[3]), "r"(b0), "r"(b1));
}
// hi = bf16_rn(x); lo = bf16_rn(x - hi), packed pairs
__device__ __forceinline__ void split2(float x, float y, unsigned int& hw, unsigned int& lw) {
    __nv_bfloat16 hx = __float2bfloat16_rn(x);
    __nv_bfloat16 hy = __float2bfloat16_rn(y);
    __nv_bfloat162 hp; hp.x = hx; hp.y = hy;
    hw = *reinterpret_cast<unsigned int*>(&hp);
    __nv_bfloat162 lp = __floats2bfloat162_rn(x - __bfloat162float(hx),
                                              y - __bfloat162float(hy));
    lw = *reinterpret_cast<unsigned int*>(&lp);
}

// ---------------------------------------------------------------------------
// split_w: W[1024,256] fp32 -> W^T hi/lo bf16 [256][1024] (k-contiguous).
// ---------------------------------------------------------------------------
__global__ void __launch_bounds__(256)
split_w_kernel(const float* __restrict__ W) {
    int t = blockIdx.x * 256 + threadIdx.x;   // 0 .. 32767
    int n  = t >> 7;
    int k8 = t & 127;
    unsigned int hw[4], lw[4];
    #pragma unroll
    for (int p = 0; p < 4; p++) {
        float x = W[(size_t)(k8 * 8 + 2 * p)     * N_TOT + n];
        float y = W[(size_t)(k8 * 8 + 2 * p + 1) * N_TOT + n];
        split2(x, y, hw[p], lw[p]);
    }
    size_t off = (size_t)n * K_TOT + k8 * 8;
    *(uint4*)(g_Wth + off) = make_uint4(hw[0], hw[1], hw[2], hw[3]);
    *(uint4*)(g_Wtl + off) = make_uint4(lw[0], lw[1], lw[2], lw[3]);
}

// ---------------------------------------------------------------------------
// Fused GEMM: h = A@W + bias with A split to bf16 hi/lo IN-KERNEL.
// Grid (128), 256 threads (8 warps: 4m x 2n), BN=256 so A is read ONCE.
// W tiles via 2-stage cp.async from pre-split g_Wth/g_Wtl.
// ---------------------------------------------------------------------------
__global__ void __launch_bounds__(256)
gemm_fused_kernel(const float* __restrict__ A, const float* __restrict__ bias) {
    extern __shared__ char smem[];
    const uint32_t sb = smem_u32(smem);
    const int tid  = threadIdx.x;
    const int lane = tid & 31;
    const int wid  = tid >> 5;
    const int m0 = blockIdx.x * BM;
    const int mw = (wid >> 1) * 32;   // warp m offset
    const int nw = (wid & 1) * 128;   // warp n offset

    float* bias_s = (float*)(smem + SM_BIAS);
    if (tid < BN) bias_s[tid] = bias[tid];

    float acc[2][16][4];
    #pragma unroll
    for (int i = 0; i < 2; i++)
        #pragma unroll
        for (int j = 0; j < 16; j++)
            #pragma unroll
            for (int v = 0; v < 4; v++) acc[i][j][v] = 0.f;

    // ---- W stage issue (cp.async): hi+lo tiles, 256 rows x 32 k bf16 each ----
    auto issue_w = [&](uint32_t wst, int kt) {
        const int k0 = kt * BK;
        #pragma unroll
        for (int it = 0; it < 8; it++) {
            const int tile = it >> 2;                 // 0=hi, 1=lo
            const int idx = ((it & 3) << 8) + tid;    // 0..1023
            const int row = idx >> 2, g = idx & 3;
            uint32_t dst = wst + tile * W_TILE_B + (uint32_t)(row * LDA + g * 8) * 2;
            const __nv_bfloat16* src = (tile ? g_Wtl : g_Wth) + (size_t)row * K_TOT + k0 + g * 8;
            cp_async16(dst, src);
        }
        asm volatile("cp.async.commit_group;" ::: "memory");
    };

    // A register prefetch + in-kernel split/store.
    // Each thread owns half a row-slice: row = tid>>1, k-half = (tid&1)*16.
    const int arow = tid >> 1;
    const int akh  = (tid & 1) * 16;
    const float* abase = A + (size_t)(m0 + arow) * K_TOT + akh;
    float4 pv[4];
    auto ldgA = [&](int kt) {
        const float* s = abase + kt * BK;
        pv[0] = *(const float4*)(s + 0);
        pv[1] = *(const float4*)(s + 4);
        pv[2] = *(const float4*)(s + 8);
        pv[3] = *(const float4*)(s + 12);
    };
    auto stsA = [&](uint32_t astg_off) {   // byte offset of A stage within smem
        unsigned int hw[8], lw[8];
        const float* f = (const float*)pv;
        #pragma unroll
        for (int p = 0; p < 8; p++) split2(f[2*p], f[2*p+1], hw[p], lw[p]);
        const uint32_t off = (uint32_t)(arow * LDA + akh) * 2;
        *(uint4*)(smem + astg_off + off)      = make_uint4(hw[0], hw[1], hw[2], hw[3]);
        *(uint4*)(smem + astg_off + off + 16) = make_uint4(hw[4], hw[5], hw[6], hw[7]);
        *(uint4*)(smem + astg_off + A_TILE_B + off)      = make_uint4(lw[0], lw[1], lw[2], lw[3]);
        *(uint4*)(smem + astg_off + A_TILE_B + off + 16) = make_uint4(lw[4], lw[5], lw[6], lw[7]);
    };

    const uint32_t a_row = lane & 15;
    const uint32_t a_g   = lane >> 4;

    auto compute = [&](uint32_t astg, uint32_t wst) {
        #pragma unroll
        for (int k16 = 0; k16 < 2; k16++) {
            const uint32_t aoff = (uint32_t)((mw + a_row) * LDA + k16 * 16 + a_g * 8) * 2;
            uint32_t ah0[4], ah1[4], al0[4], al1[4];
            ldsm_x4(ah0, astg + aoff);
            ldsm_x4(ah1, astg + aoff + 16 * LDA * 2);
            ldsm_x4(al0, astg + A_TILE_B + aoff);
            ldsm_x4(al1, astg + A_TILE_B + aoff + 16 * LDA * 2);
            #pragma unroll
            for (int nq = 0; nq < 8; nq++) {
                const uint32_t woff =
                    (uint32_t)((nw + nq * 16 + a_row) * LDA + k16 * 16 + a_g * 8) * 2;
                uint32_t w4[4];
                ldsm_x4(w4, wst + woff);                  // Wh
                mma16816(acc[0][2*nq],   ah0, w4[0], w4[2]);
                mma16816(acc[0][2*nq+1], ah0, w4[1], w4[3]);
                mma16816(acc[1][2*nq],   ah1, w4[0], w4[2]);
                mma16816(acc[1][2*nq+1], ah1, w4[1], w4[3]);
                mma16816(acc[0][2*nq],   al0, w4[0], w4[2]);   // Al @ Wh
                mma16816(acc[0][2*nq+1], al0, w4[1], w4[3]);
                mma16816(acc[1][2*nq],   al1, w4[0], w4[2]);
                mma16816(acc[1][2*nq+1], al1, w4[1], w4[3]);
                ldsm_x4(w4, wst + W_TILE_B + woff);       // Wl
                mma16816(acc[0][2*nq],   ah0, w4[0], w4[2]);   // Ah @ Wl
                mma16816(acc[0][2*nq+1], ah0, w4[1], w4[3]);
                mma16816(acc[1][2*nq],   ah1, w4[0], w4[2]);
                mma16816(acc[1][2*nq+1], ah1, w4[1], w4[3]);
            }
        }
    };

    // ---- prologue ----
    ldgA(0);
    issue_w(sb + SM_W0, 0);
    stsA(0);                  // stage 0 A (consumes LDG(0))
    ldgA(1);
    issue_w(sb + SM_W0 + WSTG_B, 1);
    asm volatile("cp.async.wait_group 1;" ::: "memory");  // W(0) done
    __syncthreads();
    compute(sb, sb + SM_W0);
    __syncthreads();

    for (int kt = 1; kt < KTILES; kt++) {
        const int s = kt & 1;
        const uint32_t astg = sb + s * ASTG_B;
        const uint32_t wst  = sb + SM_W0 + s * WSTG_B;
        stsA(s * ASTG_B);                 // regs hold A(kt)
        if (kt + 1 < KTILES) {
            ldgA(kt + 1);
            issue_w(sb + SM_W0 + (s ^ 1) * WSTG_B, kt + 1);
            asm volatile("cp.async.wait_group 1;" ::: "memory");  // W(kt) done
        } else {
            asm volatile("cp.async.wait_group 0;" ::: "memory");
        }
        __syncthreads();
        compute(astg, wst);
        __syncthreads();
    }

    // ---- epilogue: bias + store fp32 h ----
    const int crow = lane >> 2;        // 0..7
    const int ccol = (lane & 3) * 2;   // 0,2,4,6
    #pragma unroll
    for (int mt = 0; mt < 2; mt++) {
        const int mrow = m0 + mw + mt * 16 + crow;
        #pragma unroll
        for (int nt = 0; nt < 16; nt++) {
            const int nc = nw + nt * 8 + ccol;
            const float b0 = bias_s[nc], b1 = bias_s[nc + 1];
            float2 v0 = make_float2(acc[mt][nt][0] + b0, acc[mt][nt][1] + b1);
            float2 v1 = make_float2(acc[mt][nt][2] + b0, acc[mt][nt][3] + b1);
            *(float2*)&g_h[(size_t)mrow * N_TOT + nc] = v0;
            *(float2*)&g_h[(size_t)(mrow + 8) * N_TOT + nc] = v1;
        }
    }
}

// ---------------------------------------------------------------------------
// Gather: one q per 128-thread half-block, both sets per thread (MLP=2).
// ---------------------------------------------------------------------------
__global__ void __launch_bounds__(256)
gather_kernel(const int* __restrict__ qb,
              const int* __restrict__ s1, const int* __restrict__ e1,
              const int* __restrict__ s2, const int* __restrict__ e2,
              float* __restrict__ out) {
    const int q = blockIdx.x * 2 + (threadIdx.x >> 7);
    const int t = threadIdx.x & 127;
    const int b = __ldg(&qb[q]);
    const int sA = __ldg(&s1[q]), eA = __ldg(&e1[q]);
    const int sB = __ldg(&s2[q]), eB = __ldg(&e2[q]);
    const int col = (t & 63) * 4;
    const size_t brow = (size_t)b * S_LEN;

    float4 v0 = make_float4(0.f, 0.f, 0.f, 0.f);
    float4 v1 = v0;
    if (eA >= sA) {
        const int pos = (t < 64) ? sA : eA;
        v0 = *(const float4*)&g_h[(brow + pos) * N_TOT + col];
    }
    if (eB >= sB) {
        const int pos = (t < 64) ? sB : eB;
        v1 = *(const float4*)&g_h[(brow + pos) * N_TOT + col];
    }
    *(float4*)(out + ((size_t)q)          * (2 * P_DIM) + t * 4) = v0;
    *(float4*)(out + ((size_t)NQ_DIM + q) * (2 * P_DIM) + t * 4) = v1;
}

// ---------------------------------------------------------------------------
// Inputs: flag, encoded_input, start_ids_1, end_ids_1, query_batch_idx,
// start_ids_2, end_ids_2, W, b. Output: res1 then res2, each [NQ, 512] fp32.
// ---------------------------------------------------------------------------
extern "C" void kernel_launch(void* const* d_in, const int* in_sizes, int n_in,
                              void* d_out, int out_size) {
    const float* enc  = (const float*)d_in[1];
    const int*   s1   = (const int*)d_in[2];
    const int*   e1   = (const int*)d_in[3];
    const int*   qb   = (const int*)d_in[4];
    const int*   s2   = (const int*)d_in[5];
    const int*   e2   = (const int*)d_in[6];
    const float* W    = (const float*)d_in[7];
    const float* bias = (const float*)d_in[8];
    float* out = (float*)d_out;

    cudaFuncSetAttribute(gemm_fused_kernel,
                         cudaFuncAttributeMaxDynamicSharedMemorySize, SMEM_GEMM);

    split_w_kernel<<<(N_TOT * (K_TOT / 8)) / 256, 256>>>(W);     // 128 blocks
    gemm_fused_kernel<<<M_TOT / BM, 256, SMEM_GEMM>>>(enc, bias);
    gather_kernel<<<NQ_DIM / 2, 256>>>(qb, s1, e1, s2, e2, out);
}

// round 12
// speedup vs baseline: 2.6379x; 1.4024x over previous
#include <cuda_runtime.h>
#include <cuda_fp16.h>
#include <stdint.h>

// Problem dims (fixed)
#define B_DIM   8
#define S_LEN   2048
#define D_DIM   1024
#define P_DIM   256
#define NQ_DIM  8192
#define M_TOT   16384
#define N_TOT   256
#define K_TOT   1024

// GEMM tiling: BM=128, BN=256 (full N), BK=32
#define BM      128
#define BN      256
#define BK      32
#define KTILES  (K_TOT / BK)        // 32
#define LDA     40                  // fp16 elems per smem row (32 data + 8 pad) -> 80B stride

#define A_TILE_B  (BM * LDA * 2)    // 10240  (one of Ah / Al)
#define W_TILE_B  (BN * LDA * 2)    // 20480  (single fp16 W tile)
#define ASTG_B    (2 * A_TILE_B)    // 20480  per stage (Ah + Al)
#define SM_W0     (2 * ASTG_B)      // 40960  (W: 3 stages follow)
#define SM_BIAS   (SM_W0 + 3 * W_TILE_B)   // 102400
#define SMEM_GEMM (SM_BIAS + 1024)         // 103424

// Device scratch (static: no allocations allowed)
__device__ __align__(16) __half g_Wt[(size_t)N_TOT * K_TOT];        // 512 KB (W^T fp16)
__device__ __align__(16) float  g_h[(size_t)M_TOT * N_TOT];         // 16 MB

// ---------------- helpers (baseline PTX only: sm_80-level) ----------------
__device__ __forceinline__ uint32_t smem_u32(const void* p) {
    uint32_t a;
    asm("{ .reg .u64 t; cvta.to.shared.u64 t, %1; cvt.u32.u64 %0, t; }" : "=r"(a) : "l"(p));
    return a;
}
__device__ __forceinline__ void cp_async16(uint32_t dst, const void* src) {
    asm volatile("cp.async.cg.shared.global [%0], [%1], 16;" :: "r"(dst), "l"(src) : "memory");
}
__device__ __forceinline__ void ldsm_x4(uint32_t* r, uint32_t addr) {
    asm volatile("ldmatrix.sync.aligned.m8n8.x4.shared.b16 {%0,%1,%2,%3}, [%4];"
                 : "=r"(r[0]), "=r"(r[1]), "=r"(r[2]), "=r"(r[3]) : "r"(addr));
}
__device__ __forceinline__ void mma16816(float* c, const uint32_t* a, uint32_t b0, uint32_t b1) {
    asm volatile(
        "mma.sync.aligned.m16n8k16.row.col.f32.f16.f16.f32 "
        "{%0,%1,%2,%3}, {%4,%5,%6,%7}, {%8,%9}, {%0,%1,%2,%3};"
        : "+f"(c[0]), "+f"(c[1]), "+f"(c[2]), "+f"(c[3])
        : "r"(a[0]), "r"(a[1]), "r"(a[2]), "r"(a[3]), "r"(b0), "r"(b1));
}
// fp16 split: hi = h_rn(x); lo = h_rn(x - hi). Packed pairs.
__device__ __forceinline__ void split2h(float x, float y, unsigned int& hw, unsigned int& lw) {
    __half hx = __float2half_rn(x);
    __half hy = __float2half_rn(y);
    __half2 hp = __halves2half2(hx, hy);
    hw = *reinterpret_cast<unsigned int*>(&hp);
    __half2 lp = __floats2half2_rn(x - __half2float(hx), y - __half2float(hy));
    lw = *reinterpret_cast<unsigned int*>(&lp);
}

// ---------------------------------------------------------------------------
// split_w: W[1024,256] fp32 -> W^T fp16 [256][1024] (k-contiguous).
// 4 elems/thread, 256 blocks for latency hiding.
// ---------------------------------------------------------------------------
__global__ void __launch_bounds__(256)
split_w_kernel(const float* __restrict__ W) {
    int t = blockIdx.x * 256 + threadIdx.x;   // 0 .. 65535
    int n  = t >> 8;
    int k4 = t & 255;
    unsigned int hw[2];
    #pragma unroll
    for (int p = 0; p < 2; p++) {
        float x = W[(size_t)(k4 * 4 + 2 * p)     * N_TOT + n];
        float y = W[(size_t)(k4 * 4 + 2 * p + 1) * N_TOT + n];
        __half2 hp = __floats2half2_rn(x, y);
        hw[p] = *reinterpret_cast<unsigned int*>(&hp);
    }
    *(uint2*)(g_Wt + (size_t)n * K_TOT + k4 * 4) = make_uint2(hw[0], hw[1]);
}

// ---------------------------------------------------------------------------
// Fused GEMM: h = A@W + bias, A split to fp16 hi/lo IN-KERNEL (2 MMA terms).
// Grid (128), 256 threads (8 warps: 4m x 2n). A: 2-stage (reg-staged LDG ->
// convert -> STS). W: 3-stage cp.async from g_Wt. ONE barrier per k-tile.
// ---------------------------------------------------------------------------
__global__ void __launch_bounds__(256)
gemm_fused_kernel(const float* __restrict__ A, const float* __restrict__ bias) {
    extern __shared__ char smem[];
    const uint32_t sb = smem_u32(smem);
    const int tid  = threadIdx.x;
    const int lane = tid & 31;
    const int wid  = tid >> 5;
    const int m0 = blockIdx.x * BM;
    const int mw = (wid >> 1) * 32;   // warp m offset
    const int nw = (wid & 1) * 128;   // warp n offset

    float* bias_s = (float*)(smem + SM_BIAS);
    if (tid < BN) bias_s[tid] = bias[tid];

    float acc[2][16][4];
    #pragma unroll
    for (int i = 0; i < 2; i++)
        #pragma unroll
        for (int j = 0; j < 16; j++)
            #pragma unroll
            for (int v = 0; v < 4; v++) acc[i][j][v] = 0.f;

    // ---- W stage issue (cp.async): 256 rows x 32 k fp16 ----
    auto issue_w = [&](int slot3, int kt) {
        const uint32_t wst = sb + SM_W0 + slot3 * W_TILE_B;
        const int k0 = kt * BK;
        #pragma unroll
        for (int it = 0; it < 4; it++) {
            const int idx = (it << 8) + tid;          // 0..1023
            const int row = idx >> 2, g = idx & 3;
            uint32_t dst = wst + (uint32_t)(row * LDA + g * 8) * 2;
            cp_async16(dst, g_Wt + (size_t)row * K_TOT + k0 + g * 8);
        }
        asm volatile("cp.async.commit_group;" ::: "memory");
    };

    // A register prefetch + in-kernel fp16 split/store.
    const int arow = tid >> 1;
    const int akh  = (tid & 1) * 16;
    const float* abase = A + (size_t)(m0 + arow) * K_TOT + akh;
    float4 pv[4];
    auto ldgA = [&](int kt) {
        const float* s = abase + kt * BK;
        pv[0] = *(const float4*)(s + 0);
        pv[1] = *(const float4*)(s + 4);
        pv[2] = *(const float4*)(s + 8);
        pv[3] = *(const float4*)(s + 12);
    };
    auto stsA = [&](int slot2) {
        const uint32_t astg_off = slot2 * ASTG_B;
        unsigned int hw[8], lw[8];
        const float* f = (const float*)pv;
        #pragma unroll
        for (int p = 0; p < 8; p++) split2h(f[2*p], f[2*p+1], hw[p], lw[p]);
        const uint32_t off = (uint32_t)(arow * LDA + akh) * 2;
        *(uint4*)(smem + astg_off + off)      = make_uint4(hw[0], hw[1], hw[2], hw[3]);
        *(uint4*)(smem + astg_off + off + 16) = make_uint4(hw[4], hw[5], hw[6], hw[7]);
        *(uint4*)(smem + astg_off + A_TILE_B + off)      = make_uint4(lw[0], lw[1], lw[2], lw[3]);
        *(uint4*)(smem + astg_off + A_TILE_B + off + 16) = make_uint4(lw[4], lw[5], lw[6], lw[7]);
    };

    const uint32_t a_row = lane & 15;
    const uint32_t a_g   = lane >> 4;

    auto compute = [&](int slot2, int slot3) {
        const uint32_t astg = sb + slot2 * ASTG_B;
        const uint32_t wst  = sb + SM_W0 + slot3 * W_TILE_B;
        #pragma unroll
        for (int k16 = 0; k16 < 2; k16++) {
            const uint32_t aoff = (uint32_t)((mw + a_row) * LDA + k16 * 16 + a_g * 8) * 2;
            uint32_t ah0[4], ah1[4], al0[4], al1[4];
            ldsm_x4(ah0, astg + aoff);
            ldsm_x4(ah1, astg + aoff + 16 * LDA * 2);
            ldsm_x4(al0, astg + A_TILE_B + aoff);
            ldsm_x4(al1, astg + A_TILE_B + aoff + 16 * LDA * 2);

            // W frags double-buffered in regs: LDSM one nq ahead of its MMAs
            uint32_t wa[4], wb[4];
            auto woff = [&](int nq) {
                return (uint32_t)((nw + nq * 16 + a_row) * LDA + k16 * 16 + a_g * 8) * 2;
            };
            ldsm_x4(wa, wst + woff(0));
            #pragma unroll
            for (int nq = 0; nq < 8; nq++) {
                uint32_t* wc = (nq & 1) ? wb : wa;
                uint32_t* wn = (nq & 1) ? wa : wb;
                if (nq < 7) ldsm_x4(wn, wst + woff(nq + 1));
                mma16816(acc[0][2*nq],   ah0, wc[0], wc[2]);
                mma16816(acc[0][2*nq+1], ah0, wc[1], wc[3]);
                mma16816(acc[1][2*nq],   ah1, wc[0], wc[2]);
                mma16816(acc[1][2*nq+1], ah1, wc[1], wc[3]);
                mma16816(acc[0][2*nq],   al0, wc[0], wc[2]);   // Al @ W
                mma16816(acc[0][2*nq+1], al0, wc[1], wc[3]);
                mma16816(acc[1][2*nq],   al1, wc[0], wc[2]);
                mma16816(acc[1][2*nq+1], al1, wc[1], wc[3]);
            }
        }
    };

    // ---- prologue: stage A(0), A(1) regs, W(0), W(1) ----
    ldgA(0);
    issue_w(0, 0);
    issue_w(1, 1);
    stsA(0);                  // consumes LDG(0)
    ldgA(1);
    asm volatile("cp.async.wait_group 1;" ::: "memory");  // W(0) done
    __syncthreads();

    // ---- mainloop: ONE barrier per kt (W 3-stage makes reuse distance 2) ----
    for (int kt = 0; kt < KTILES; kt++) {
        compute(kt & 1, kt % 3);
        if (kt + 1 < KTILES) {
            stsA((kt + 1) & 1);           // regs hold A(kt+1)
            if (kt + 2 < KTILES) {
                ldgA(kt + 2);
                issue_w((kt + 2) % 3, kt + 2);
                asm volatile("cp.async.wait_group 1;" ::: "memory");  // W(kt+1) done
            } else {
                asm volatile("cp.async.wait_group 0;" ::: "memory");
            }
            __syncthreads();
        }
    }

    // ---- epilogue: bias + store fp32 h ----
    const int crow = lane >> 2;        // 0..7
    const int ccol = (lane & 3) * 2;   // 0,2,4,6
    #pragma unroll
    for (int mt = 0; mt < 2; mt++) {
        const int mrow = m0 + mw + mt * 16 + crow;
        #pragma unroll
        for (int nt = 0; nt < 16; nt++) {
            const int nc = nw + nt * 8 + ccol;
            const float b0 = bias_s[nc], b1 = bias_s[nc + 1];
            float2 v0 = make_float2(acc[mt][nt][0] + b0, acc[mt][nt][1] + b1);
            float2 v1 = make_float2(acc[mt][nt][2] + b0, acc[mt][nt][3] + b1);
            *(float2*)&g_h[(size_t)mrow * N_TOT + nc] = v0;
            *(float2*)&g_h[(size_t)(mrow + 8) * N_TOT + nc] = v1;
        }
    }
}

// ---------------------------------------------------------------------------
// Gather: one q per 128-thread half-block, both sets per thread (MLP=2).
// ---------------------------------------------------------------------------
__global__ void __launch_bounds__(256)
gather_kernel(const int* __restrict__ qb,
              const int* __restrict__ s1, const int* __restrict__ e1,
              const int* __restrict__ s2, const int* __restrict__ e2,
              float* __restrict__ out) {
    const int q = blockIdx.x * 2 + (threadIdx.x >> 7);
    const int t = threadIdx.x & 127;
    const int b = __ldg(&qb[q]);
    const int sA = __ldg(&s1[q]), eA = __ldg(&e1[q]);
    const int sB = __ldg(&s2[q]), eB = __ldg(&e2[q]);
    const int col = (t & 63) * 4;
    const size_t brow = (size_t)b * S_LEN;

    float4 v0 = make_float4(0.f, 0.f, 0.f, 0.f);
    float4 v1 = v0;
    if (eA >= sA) {
        const int pos = (t < 64) ? sA : eA;
        v0 = *(const float4*)&g_h[(brow + pos) * N_TOT + col];
    }
    if (eB >= sB) {
        const int pos = (t < 64) ? sB : eB;
        v1 = *(const float4*)&g_h[(brow + pos) * N_TOT + col];
    }
    *(float4*)(out + ((size_t)q)          * (2 * P_DIM) + t * 4) = v0;
    *(float4*)(out + ((size_t)NQ_DIM + q) * (2 * P_DIM) + t * 4) = v1;
}

// ---------------------------------------------------------------------------
// Inputs: flag, encoded_input, start_ids_1, end_ids_1, query_batch_idx,
// start_ids_2, end_ids_2, W, b. Output: res1 then res2, each [NQ, 512] fp32.
// ---------------------------------------------------------------------------
extern "C" void kernel_launch(void* const* d_in, const int* in_sizes, int n_in,
                              void* d_out, int out_size) {
    const float* enc  = (const float*)d_in[1];
    const int*   s1   = (const int*)d_in[2];
    const int*   e1   = (const int*)d_in[3];
    const int*   qb   = (const int*)d_in[4];
    const int*   s2   = (const int*)d_in[5];
    const int*   e2   = (const int*)d_in[6];
    const float* W    = (const float*)d_in[7];
    const float* bias = (const float*)d_in[8];
    float* out = (float*)d_out;

    cudaFuncSetAttribute(gemm_fused_kernel,
                         cudaFuncAttributeMaxDynamicSharedMemorySize, SMEM_GEMM);

    split_w_kernel<<<N_TOT * (K_TOT / 4) / 256, 256>>>(W);       // 256 blocks
    gemm_fused_kernel<<<M_TOT / BM, 256, SMEM_GEMM>>>(enc, bias);
    gather_kernel<<<NQ_DIM / 2, 256>>>(qb, s1, e1, s2, e2, out);
}

// round 13
// speedup vs baseline: 2.8599x; 1.0842x over previous
#include <cuda_runtime.h>
#include <cuda_fp16.h>
#include <stdint.h>

// Problem dims (fixed)
#define B_DIM   8
#define S_LEN   2048
#define D_DIM   1024
#define P_DIM   256
#define NQ_DIM  8192
#define M_TOT   16384
#define N_TOT   256
#define K_TOT   1024

// GEMM tiling: BM=128, BN=256 (full N), BK=32, 512 threads (16 warps 4m x 4n)
#define BM      128
#define BN      256
#define BK      32
#define KTILES  (K_TOT / BK)        // 32
#define LDA     40                  // fp16 elems per smem row (32 data + 8 pad)
#define NTHR    512

#define A_TILE_B  (BM * LDA * 2)    // 10240  (one of Ah / Al)
#define W_TILE_B  (BN * LDA * 2)    // 20480
#define ASTG_B    (2 * A_TILE_B)    // 20480  per stage (Ah + Al)
#define SM_W0     (2 * ASTG_B)      // 40960  (W: 3 stages follow)
#define SM_BIAS   (SM_W0 + 3 * W_TILE_B)   // 102400
#define SMEM_GEMM (SM_BIAS + 1024)         // 103424

// Device scratch (static: no allocations allowed)
__device__ __align__(16) __half g_Wt[(size_t)N_TOT * K_TOT];        // 512 KB (W^T fp16)
__device__ __align__(16) float  g_h[(size_t)M_TOT * N_TOT];         // 16 MB

// ---------------- helpers (baseline PTX only: sm_80-level) ----------------
__device__ __forceinline__ uint32_t smem_u32(const void* p) {
    uint32_t a;
    asm("{ .reg .u64 t; cvta.to.shared.u64 t, %1; cvt.u32.u64 %0, t; }" : "=r"(a) : "l"(p));
    return a;
}
__device__ __forceinline__ void cp_async16(uint32_t dst, const void* src) {
    asm volatile("cp.async.cg.shared.global [%0], [%1], 16;" :: "r"(dst), "l"(src) : "memory");
}
__device__ __forceinline__ void ldsm_x4(uint32_t* r, uint32_t addr) {
    asm volatile("ldmatrix.sync.aligned.m8n8.x4.shared.b16 {%0,%1,%2,%3}, [%4];"
                 : "=r"(r[0]), "=r"(r[1]), "=r"(r[2]), "=r"(r[3]) : "r"(addr));
}
__device__ __forceinline__ void mma16816(float* c, const uint32_t* a, uint32_t b0, uint32_t b1) {
    asm volatile(
        "mma.sync.aligned.m16n8k16.row.col.f32.f16.f16.f32 "
        "{%0,%1,%2,%3}, {%4,%5,%6,%7}, {%8,%9}, {%0,%1,%2,%3};"
        : "+f"(c[0]), "+f"(c[1]), "+f"(c[2]), "+f"(c[3])
        : "r"(a[0]), "r"(a[1]), "r"(a[2]), "r"(a[3]), "r"(b0), "r"(b1));
}
// fp16 split: hi = h_rn(x); lo = h_rn(x - hi). Packed pairs.
__device__ __forceinline__ void split2h(float x, float y, unsigned int& hw, unsigned int& lw) {
    __half hx = __float2half_rn(x);
    __half hy = __float2half_rn(y);
    __half2 hp = __halves2half2(hx, hy);
    hw = *reinterpret_cast<unsigned int*>(&hp);
    __half2 lp = __floats2half2_rn(x - __half2float(hx), y - __half2float(hy));
    lw = *reinterpret_cast<unsigned int*>(&lp);
}

// ---------------------------------------------------------------------------
// split_w: W[1024,256] fp32 -> W^T fp16 [256][1024]. COALESCED reads
// (consecutive n within a warp), 2B scattered writes (fire-and-forget).
// Each thread: one k, four consecutive n (one float4 read).
// ---------------------------------------------------------------------------
__global__ void __launch_bounds__(256)
split_w_kernel(const float* __restrict__ W) {
    int t = blockIdx.x * 256 + threadIdx.x;   // 0 .. 65535
    int k  = t >> 6;                          // 0..1023
    int n4 = (t & 63) * 4;                    // 0..252
    float4 v = *(const float4*)(W + (size_t)k * N_TOT + n4);
    g_Wt[(size_t)(n4 + 0) * K_TOT + k] = __float2half_rn(v.x);
    g_Wt[(size_t)(n4 + 1) * K_TOT + k] = __float2half_rn(v.y);
    g_Wt[(size_t)(n4 + 2) * K_TOT + k] = __float2half_rn(v.z);
    g_Wt[(size_t)(n4 + 3) * K_TOT + k] = __float2half_rn(v.w);
}

// ---------------------------------------------------------------------------
// Fused GEMM: h = A@W + bias, A split to fp16 hi/lo IN-KERNEL (2 MMA terms).
// Grid (128), 512 threads (16 warps: 4m x 4n, warp tile 32x64).
// A: 2-stage (reg-staged LDG -> convert -> STS). W: 3-stage cp.async.
// ONE barrier per k-tile.
// ---------------------------------------------------------------------------
__global__ void __launch_bounds__(NTHR, 1)
gemm_fused_kernel(const float* __restrict__ A, const float* __restrict__ bias) {
    extern __shared__ char smem[];
    const uint32_t sb = smem_u32(smem);
    const int tid  = threadIdx.x;
    const int lane = tid & 31;
    const int wid  = tid >> 5;
    const int m0 = blockIdx.x * BM;
    const int mw = (wid >> 2) * 32;   // warp m offset
    const int nw = (wid & 3) * 64;    // warp n offset

    float* bias_s = (float*)(smem + SM_BIAS);
    if (tid < BN) bias_s[tid] = bias[tid];

    float acc[2][8][4];
    #pragma unroll
    for (int i = 0; i < 2; i++)
        #pragma unroll
        for (int j = 0; j < 8; j++)
            #pragma unroll
            for (int v = 0; v < 4; v++) acc[i][j][v] = 0.f;

    // ---- W stage issue (cp.async): 256 rows x 32 k fp16, 2 granules/thread ----
    auto issue_w = [&](int slot3, int kt) {
        const uint32_t wst = sb + SM_W0 + slot3 * W_TILE_B;
        const int k0 = kt * BK;
        #pragma unroll
        for (int it = 0; it < 2; it++) {
            const int idx = (it << 9) + tid;          // 0..1023
            const int row = idx >> 2, g = idx & 3;
            uint32_t dst = wst + (uint32_t)(row * LDA + g * 8) * 2;
            cp_async16(dst, g_Wt + (size_t)row * K_TOT + k0 + g * 8);
        }
        asm volatile("cp.async.commit_group;" ::: "memory");
    };

    // A register prefetch + in-kernel fp16 split/store. 8 floats/thread:
    // row = tid>>2 (0..127), k-quarter = (tid&3)*8.
    const int arow = tid >> 2;
    const int akq  = (tid & 3) * 8;
    const float* abase = A + (size_t)(m0 + arow) * K_TOT + akq;
    float4 pv[2];
    auto ldgA = [&](int kt) {
        const float* s = abase + kt * BK;
        pv[0] = *(const float4*)(s + 0);
        pv[1] = *(const float4*)(s + 4);
    };
    auto stsA = [&](int slot2) {
        const uint32_t astg_off = slot2 * ASTG_B;
        unsigned int hw[4], lw[4];
        const float* f = (const float*)pv;
        #pragma unroll
        for (int p = 0; p < 4; p++) split2h(f[2*p], f[2*p+1], hw[p], lw[p]);
        const uint32_t off = (uint32_t)(arow * LDA + akq) * 2;
        *(uint4*)(smem + astg_off + off)             = make_uint4(hw[0], hw[1], hw[2], hw[3]);
        *(uint4*)(smem + astg_off + A_TILE_B + off)  = make_uint4(lw[0], lw[1], lw[2], lw[3]);
    };

    const uint32_t a_row = lane & 15;
    const uint32_t a_g   = lane >> 4;

    auto compute = [&](int slot2, int slot3) {
        const uint32_t astg = sb + slot2 * ASTG_B;
        const uint32_t wst  = sb + SM_W0 + slot3 * W_TILE_B;
        #pragma unroll
        for (int k16 = 0; k16 < 2; k16++) {
            const uint32_t aoff = (uint32_t)((mw + a_row) * LDA + k16 * 16 + a_g * 8) * 2;
            uint32_t ah0[4], ah1[4], al0[4], al1[4];
            ldsm_x4(ah0, astg + aoff);
            ldsm_x4(ah1, astg + aoff + 16 * LDA * 2);
            ldsm_x4(al0, astg + A_TILE_B + aoff);
            ldsm_x4(al1, astg + A_TILE_B + aoff + 16 * LDA * 2);

            // W frags double-buffered in regs: LDSM one nq ahead of its MMAs
            uint32_t wa[4], wb[4];
            auto woff = [&](int nq) {
                return (uint32_t)((nw + nq * 16 + a_row) * LDA + k16 * 16 + a_g * 8) * 2;
            };
            ldsm_x4(wa, wst + woff(0));
            #pragma unroll
            for (int nq = 0; nq < 4; nq++) {
                uint32_t* wc = (nq & 1) ? wb : wa;
                uint32_t* wn = (nq & 1) ? wa : wb;
                if (nq < 3) ldsm_x4(wn, wst + woff(nq + 1));
                mma16816(acc[0][2*nq],   ah0, wc[0], wc[2]);
                mma16816(acc[0][2*nq+1], ah0, wc[1], wc[3]);
                mma16816(acc[1][2*nq],   ah1, wc[0], wc[2]);
                mma16816(acc[1][2*nq+1], ah1, wc[1], wc[3]);
                mma16816(acc[0][2*nq],   al0, wc[0], wc[2]);   // Al @ W
                mma16816(acc[0][2*nq+1], al0, wc[1], wc[3]);
                mma16816(acc[1][2*nq],   al1, wc[0], wc[2]);
                mma16816(acc[1][2*nq+1], al1, wc[1], wc[3]);
            }
        }
    };

    // ---- prologue: stage A(0), A(1) regs, W(0), W(1) ----
    ldgA(0);
    issue_w(0, 0);
    issue_w(1, 1);
    stsA(0);                  // consumes LDG(0)
    ldgA(1);
    asm volatile("cp.async.wait_group 1;" ::: "memory");  // W(0) done
    __syncthreads();

    // ---- mainloop: ONE barrier per kt (W 3-stage -> reuse distance 2) ----
    for (int kt = 0; kt < KTILES; kt++) {
        compute(kt & 1, kt % 3);
        if (kt + 1 < KTILES) {
            stsA((kt + 1) & 1);           // regs hold A(kt+1)
            if (kt + 2 < KTILES) {
                ldgA(kt + 2);
                issue_w((kt + 2) % 3, kt + 2);
                asm volatile("cp.async.wait_group 1;" ::: "memory");  // W(kt+1) done
            } else {
                asm volatile("cp.async.wait_group 0;" ::: "memory");
            }
            __syncthreads();
        }
    }

    // ---- epilogue: bias + store fp32 h ----
    const int crow = lane >> 2;        // 0..7
    const int ccol = (lane & 3) * 2;   // 0,2,4,6
    #pragma unroll
    for (int mt = 0; mt < 2; mt++) {
        const int mrow = m0 + mw + mt * 16 + crow;
        #pragma unroll
        for (int nt = 0; nt < 8; nt++) {
            const int nc = nw + nt * 8 + ccol;
            const float b0 = bias_s[nc], b1 = bias_s[nc + 1];
            float2 v0 = make_float2(acc[mt][nt][0] + b0, acc[mt][nt][1] + b1);
            float2 v1 = make_float2(acc[mt][nt][2] + b0, acc[mt][nt][3] + b1);
            *(float2*)&g_h[(size_t)mrow * N_TOT + nc] = v0;
            *(float2*)&g_h[(size_t)(mrow + 8) * N_TOT + nc] = v1;
        }
    }
}

// ---------------------------------------------------------------------------
// Gather: 4 q per 256-thread block; each thread does 4 independent float4
// loads (s/e x set1/set2) + 4 coalesced stores. MLP = 4.
// ---------------------------------------------------------------------------
__global__ void __launch_bounds__(256)
gather_kernel(const int* __restrict__ qb,
              const int* __restrict__ s1, const int* __restrict__ e1,
              const int* __restrict__ s2, const int* __restrict__ e2,
              float* __restrict__ out) {
    const int q  = blockIdx.x * 4 + (threadIdx.x >> 6);
    const int th = threadIdx.x & 63;          // 64 threads per q
    const int col = th * 4;                   // float4 col within 256
    const int b = __ldg(&qb[q]);
    const int sA = __ldg(&s1[q]), eA = __ldg(&e1[q]);
    const int sB = __ldg(&s2[q]), eB = __ldg(&e2[q]);
    const size_t brow = (size_t)b * S_LEN;

    float4 z = make_float4(0.f, 0.f, 0.f, 0.f);
    float4 vs1 = z, ve1 = z, vs2 = z, ve2 = z;
    if (eA >= sA) {
        vs1 = *(const float4*)&g_h[(brow + sA) * N_TOT + col];
        ve1 = *(const float4*)&g_h[(brow + eA) * N_TOT + col];
    }
    if (eB >= sB) {
        vs2 = *(const float4*)&g_h[(brow + sB) * N_TOT + col];
        ve2 = *(const float4*)&g_h[(brow + eB) * N_TOT + col];
    }
    float* o1 = out + (size_t)q * (2 * P_DIM);
    float* o2 = out + ((size_t)NQ_DIM + q) * (2 * P_DIM);
    *(float4*)(o1 + col)          = vs1;
    *(float4*)(o1 + P_DIM + col)  = ve1;
    *(float4*)(o2 + col)          = vs2;
    *(float4*)(o2 + P_DIM + col)  = ve2;
}

// ---------------------------------------------------------------------------
// Inputs: flag, encoded_input, start_ids_1, end_ids_1, query_batch_idx,
// start_ids_2, end_ids_2, W, b. Output: res1 then res2, each [NQ, 512] fp32.
// ---------------------------------------------------------------------------
extern "C" void kernel_launch(void* const* d_in, const int* in_sizes, int n_in,
                              void* d_out, int out_size) {
    const float* enc  = (const float*)d_in[1];
    const int*   s1   = (const int*)d_in[2];
    const int*   e1   = (const int*)d_in[3];
    const int*   qb   = (const int*)d_in[4];
    const int*   s2   = (const int*)d_in[5];
    const int*   e2   = (const int*)d_in[6];
    const float* W    = (const float*)d_in[7];
    const float* bias = (const float*)d_in[8];
    float* out = (float*)d_out;

    cudaFuncSetAttribute(gemm_fused_kernel,
                         cudaFuncAttributeMaxDynamicSharedMemorySize, SMEM_GEMM);

    split_w_kernel<<<(K_TOT * (N_TOT / 4)) / 256, 256>>>(W);     // 256 blocks
    gemm_fused_kernel<<<M_TOT / BM, NTHR, SMEM_GEMM>>>(enc, bias);
    gather_kernel<<<NQ_DIM / 4, 256>>>(qb, s1, e1, s2, e2, out);
}